// round 1
// baseline (speedup 1.0000x reference)
#include <cuda_runtime.h>
#include <math.h>

// ---------------- problem constants ----------------
#define BATCH 4096
#define M1 147456   // B*36
#define O1 100
#define K1 25
#define M2 36864    // B*9
#define O2 225
#define K2 100
#define M3 12288    // B*3
#define O3 625
#define K3 225
#define M4 4096     // B
#define O4 1225
#define K4 625
#define EPSF 1e-12f

// ---------------- device scratch (static, allocation-free) ----------------
__device__ float g_P1[3u*M1*K1];
__device__ float g_D1[3u*M1*O1];
__device__ float g_pn1[3u*M1];
__device__ float g_P2[3u*M2*K2];
__device__ float g_D2[3u*M2*O2];
__device__ float g_pn2[3u*M2];
__device__ float g_P3[3u*M3*K3];
__device__ float g_D3[3u*M3*O3];
__device__ float g_pn3[3u*M3];
__device__ float g_P4[3u*M4*K4];
__device__ float g_D4[3u*M4*O4];
__device__ float g_pn4[3u*M4];
__device__ float g_wn1[3*O1];
__device__ float g_wn2[3*O2];
__device__ float g_wn3[3*O3];
__device__ float g_wn4[3*O4];
__device__ float g_feat[(size_t)BATCH*3675];
__device__ double g_partial[8192];
__device__ float g_istd[128];   // [0..107]=stage1 (c*36+win), 108..110 s2, 111..113 s3, 114..116 s4

__device__ __forceinline__ float* pickP(int s){ return s==1?g_P1 : s==2?g_P2 : s==3?g_P3 : g_P4; }
__device__ __forceinline__ float* pickD(int s){ return s==1?g_D1 : s==2?g_D2 : s==3?g_D3 : g_D4; }
__device__ __forceinline__ float* pickPN(int s){ return s==1?g_pn1 : s==2?g_pn2 : s==3?g_pn3 : g_pn4; }
__device__ __forceinline__ float* pickWN(int s){ return s==1?g_wn1 : s==2?g_wn2 : s==3?g_wn3 : g_wn4; }

// deterministic block reduce (sum), valid result in thread 0
__device__ __forceinline__ float blockReduceSum(float v){
    __shared__ float sh[32];
    int lane = threadIdx.x & 31;
    int wid  = threadIdx.x >> 5;
    #pragma unroll
    for (int off = 16; off; off >>= 1) v += __shfl_down_sync(0xffffffffu, v, off);
    if (lane == 0) sh[wid] = v;
    __syncthreads();
    float r = 0.f;
    if (wid == 0){
        int nw = (blockDim.x + 31) >> 5;
        r = (lane < nw) ? sh[lane] : 0.f;
        #pragma unroll
        for (int off = 16; off; off >>= 1) r += __shfl_down_sync(0xffffffffu, r, off);
    }
    __syncthreads();
    return r;
}

// ---------------- kernels ----------------

// |w_o|^2 per (channel, prototype). grid (O, 3), block 128.
__global__ void wnorm_kernel(const float* __restrict__ W, int stage, int K){
    int c = blockIdx.y, o = blockIdx.x, O = gridDim.x;
    const float* w = W + ((size_t)c*O + o)*K;
    float s = 0.f;
    for (int k = threadIdx.x; k < K; k += blockDim.x){ float v = w[k]; s += v*v; }
    float t = blockReduceSum(s);
    if (threadIdx.x == 0) pickWN(stage)[c*O + o] = t;
}

// stage-1 patch extraction + per-patch norms. grid (B, 3), block 256.
__global__ void patch1_kernel(const float* __restrict__ x){
    __shared__ float img[784];
    __shared__ float patch[900];
    int n = blockIdx.x, c = blockIdx.y;
    const float* src = x + ((size_t)n*3 + c)*784;
    for (int i = threadIdx.x; i < 784; i += blockDim.x) img[i] = src[i];
    __syncthreads();
    for (int idx = threadIdx.x; idx < 900; idx += blockDim.x){
        int win = idx / 25, k = idx % 25;
        int i = win / 6, j = win % 6, r = k / 5, cc = k % 5;
        float v = img[(4*i + r)*28 + 4*j + cc];
        patch[idx] = v;
        g_P1[((size_t)c*M1 + n*36 + win)*K1 + k] = v;
    }
    __syncthreads();
    if (threadIdx.x < 36){
        float s = 0.f;
        #pragma unroll
        for (int k = 0; k < 25; k++){ float v = patch[threadIdx.x*25 + k]; s += v*v; }
        g_pn1[(size_t)c*M1 + n*36 + threadIdx.x] = s;
    }
}

// generic distance "GEMM": D[m][o] = max(|p_m|^2 + |w_o|^2 - 2 p.w, 0) + eps
// 64x64 tile, TK=16, 256 threads, 4x4 microtile. grid (M/64, ceil(O/64), 3).
__global__ void __launch_bounds__(256) dist_kernel(int stage, const float* __restrict__ W,
                                                   int M, int O, int K){
    const int c = blockIdx.z;
    const float* __restrict__ P  = pickP(stage)  + (size_t)c*M*K;
    const float* __restrict__ pn = pickPN(stage) + (size_t)c*M;
    const float* __restrict__ wn = pickWN(stage) + (size_t)c*O;
    const float* __restrict__ Wc = W + (size_t)c*O*K;
    float* __restrict__ Dc = pickD(stage) + (size_t)c*M*O;

    __shared__ __align__(16) float As[16][64];
    __shared__ __align__(16) float Bs[16][64];

    const int m0 = blockIdx.x * 64;
    const int o0 = blockIdx.y * 64;
    const int tid = threadIdx.x;
    const int tx = tid & 15, ty = tid >> 4;

    float acc[4][4];
    #pragma unroll
    for (int i = 0; i < 4; i++)
        #pragma unroll
        for (int j = 0; j < 4; j++) acc[i][j] = 0.f;

    for (int k0 = 0; k0 < K; k0 += 16){
        #pragma unroll
        for (int i = 0; i < 4; i++){
            int l = tid + i*256;
            int r = l >> 4, cc = l & 15;
            int kk = k0 + cc;
            As[cc][r] = (kk < K) ? P[(size_t)(m0 + r)*K + kk] : 0.f;
            int oo = o0 + r;
            Bs[cc][r] = (kk < K && oo < O) ? Wc[(size_t)oo*K + kk] : 0.f;
        }
        __syncthreads();
        #pragma unroll
        for (int k = 0; k < 16; k++){
            float4 av = *reinterpret_cast<const float4*>(&As[k][ty << 2]);
            float4 bv = *reinterpret_cast<const float4*>(&Bs[k][tx << 2]);
            float a0 = av.x, a1 = av.y, a2 = av.z, a3 = av.w;
            float b0 = bv.x, b1 = bv.y, b2 = bv.z, b3 = bv.w;
            acc[0][0] += a0*b0; acc[0][1] += a0*b1; acc[0][2] += a0*b2; acc[0][3] += a0*b3;
            acc[1][0] += a1*b0; acc[1][1] += a1*b1; acc[1][2] += a1*b2; acc[1][3] += a1*b3;
            acc[2][0] += a2*b0; acc[2][1] += a2*b1; acc[2][2] += a2*b2; acc[2][3] += a2*b3;
            acc[3][0] += a3*b0; acc[3][1] += a3*b1; acc[3][2] += a3*b2; acc[3][3] += a3*b3;
        }
        __syncthreads();
    }
    float pnr[4], wnr[4];
    #pragma unroll
    for (int i = 0; i < 4; i++) pnr[i] = pn[m0 + (ty << 2) + i];
    #pragma unroll
    for (int j = 0; j < 4; j++){ int oo = o0 + (tx << 2) + j; wnr[j] = (oo < O) ? wn[oo] : 0.f; }
    #pragma unroll
    for (int i = 0; i < 4; i++){
        int m = m0 + (ty << 2) + i;
        #pragma unroll
        for (int j = 0; j < 4; j++){
            int oo = o0 + (tx << 2) + j;
            if (oo < O){
                float d2 = pnr[i] + wnr[j] - 2.f*acc[i][j];
                Dc[(size_t)m*O + oo] = fmaxf(d2, 0.f) + EPSF;
            }
        }
    }
}

// deterministic partial sums of (sum dist, sum dist^2) per group.
// grid (chunks, G, 3), block 256. rows of group g are m = r*G + g.
__global__ void reduce_kernel(int stage, int M, int O, int G, int chunks){
    int c = blockIdx.z, g = blockIdx.y, chunk = blockIdx.x;
    const float* Dc = pickD(stage) + (size_t)c*M*O;
    int rpg = M / G;
    int rpc = (rpg + chunks - 1) / chunks;
    int r0 = chunk * rpc;
    int r1 = min(r0 + rpc, rpg);
    float s1 = 0.f, s2 = 0.f;
    for (int r = r0; r < r1; r++){
        const float* row = Dc + ((size_t)(r*G + g))*O;
        for (int o = threadIdx.x; o < O; o += blockDim.x){
            float d2 = row[o];          // = dist^2 exactly
            s2 += d2;
            s1 += sqrtf(d2);
        }
    }
    __shared__ double sh1[256], sh2[256];
    sh1[threadIdx.x] = (double)s1;
    sh2[threadIdx.x] = (double)s2;
    __syncthreads();
    for (int st = 128; st; st >>= 1){
        if (threadIdx.x < st){
            sh1[threadIdx.x] += sh1[threadIdx.x + st];
            sh2[threadIdx.x] += sh2[threadIdx.x + st];
        }
        __syncthreads();
    }
    if (threadIdx.x == 0){
        int slot = (c*G + g)*chunks + chunk;
        g_partial[2*slot]     = sh1[0];
        g_partial[2*slot + 1] = sh2[0];
    }
}

// finalize: istd = 0.5 / var (unbiased). grid 3*G blocks.
__global__ void std_kernel(int G, int chunks, double Mcnt, int base){
    if (threadIdx.x != 0) return;
    int idx = blockIdx.x;   // c*G + g
    double S1 = 0.0, S2 = 0.0;
    for (int i = 0; i < chunks; i++){
        S1 += g_partial[2*(idx*chunks + i)];
        S2 += g_partial[2*(idx*chunks + i) + 1];
    }
    double var = (S2 - S1*S1/Mcnt) / (Mcnt - 1.0);
    g_istd[base + idx] = (float)(0.5 / var);
}

// stage1 epilogue: exp + crelu(0.4) + 2x2 alpha pooling -> P2 rows + norms.
// grid (M2, 3), block 128. n2 = n*9 + h*3 + w.
__global__ void apply1_kernel(const float* __restrict__ cb){
    int c = blockIdx.y, n2 = blockIdx.x;
    int n = n2 / 9, hw = n2 % 9, h = hw / 3, w = hw % 3;
    const float* D1c = g_D1 + (size_t)c*M1*O1;
    const float* is  = g_istd + c*36;
    float bias = cb[0];
    const float A00 = 0.729f, A01 = 0.81f, A10 = 0.9f, A11 = 1.0f;
    int o = threadIdx.x;
    float pooled = 0.f;
    if (o < O1){
        float s = 0.f;
        #pragma unroll
        for (int a = 0; a < 2; a++){
            #pragma unroll
            for (int b = 0; b < 2; b++){
                int win = (2*h + a)*6 + (2*w + b);
                float d2 = D1c[((size_t)(n*36 + win))*O1 + o];
                float y = expf(-d2 * is[win]);
                y = (y >= bias) ? y : 0.f;
                float al = (a == 0) ? ((b == 0) ? A00 : A01) : ((b == 0) ? A10 : A11);
                s += al * y;
            }
        }
        pooled = 0.25f * s;
        g_P2[((size_t)c*M2 + n2)*K2 + o] = pooled;
    }
    float t = blockReduceSum(pooled*pooled);
    if (threadIdx.x == 0) g_pn2[(size_t)c*M2 + n2] = t;
}

// stage2 epilogue: exp + crelu(0.1) + pool over w with alpha [0.81,0.9,1.0]/3.
// grid (M3, 3), block 256. n3 = b*3 + h, src rows n2 = b*9 + h*3 + w.
__global__ void apply2_kernel(const float* __restrict__ cb){
    int c = blockIdx.y, n3 = blockIdx.x;
    int b = n3 / 3, h = n3 % 3;
    const float* D2c = g_D2 + (size_t)c*M2*O2;
    float is = g_istd[108 + c];
    float bias = cb[1];
    const float AW[3] = {0.81f, 0.9f, 1.0f};
    int k = threadIdx.x;
    float v = 0.f;
    if (k < O2){
        float s = 0.f;
        #pragma unroll
        for (int w = 0; w < 3; w++){
            int n2 = b*9 + h*3 + w;
            float d2 = D2c[(size_t)n2*O2 + k];
            float y = expf(-d2 * is);
            y = (y >= bias) ? y : 0.f;
            s += AW[w] * y;
        }
        v = s * (1.f/3.f);
        g_P3[((size_t)c*M3 + n3)*K3 + k] = v;
    }
    float t = blockReduceSum(v*v);
    if (threadIdx.x == 0) g_pn3[(size_t)c*M3 + n3] = t;
}

// stage3 epilogue: exp + crelu(0.01) + pool over h with alpha [0.81,0.9,1.0]/3.
// grid (B, 3), block 256. src rows n3 = b*3 + h.
__global__ void apply3_kernel(const float* __restrict__ cb){
    int c = blockIdx.y, b = blockIdx.x;
    const float* D3c = g_D3 + (size_t)c*M3*O3;
    float is = g_istd[111 + c];
    float bias = cb[2];
    const float AH[3] = {0.81f, 0.9f, 1.0f};
    float sq = 0.f;
    for (int k = threadIdx.x; k < O3; k += blockDim.x){
        float s = 0.f;
        #pragma unroll
        for (int h = 0; h < 3; h++){
            float d2 = D3c[((size_t)(b*3 + h))*O3 + k];
            float y = expf(-d2 * is);
            y = (y >= bias) ? y : 0.f;
            s += AH[h] * y;
        }
        float v = s * (1.f/3.f);
        g_P4[((size_t)c*M4 + b)*K4 + k] = v;
        sq += v*v;
    }
    float t = blockReduceSum(sq);
    if (threadIdx.x == 0) g_pn4[(size_t)c*M4 + b] = t;
}

// stage4 epilogue: exp + crelu(0.01) -> feat[b][c*1225+o]. grid-stride.
__global__ void apply4_kernel(const float* __restrict__ cb){
    float bias = cb[3];
    const size_t total = (size_t)3*M4*O4;
    for (size_t idx = (size_t)blockIdx.x*blockDim.x + threadIdx.x; idx < total;
         idx += (size_t)gridDim.x*blockDim.x){
        int c = (int)(idx / ((size_t)M4*O4));
        int r = (int)(idx % ((size_t)M4*O4));
        int b = r / O4, o = r % O4;
        float d2 = g_D4[idx];
        float y = expf(-d2 * g_istd[114 + c]);
        y = (y >= bias) ? y : 0.f;
        g_feat[(size_t)b*3675 + c*1225 + o] = y;
    }
}

// FC: out[b][j] = feat[b] . fcw[j] + fcb[j]. grid B, block 256.
__global__ void fc_kernel(const float* __restrict__ fcw, const float* __restrict__ fcb,
                          float* __restrict__ out){
    int b = blockIdx.x;
    const float* f = g_feat + (size_t)b*3675;
    float part[10];
    #pragma unroll
    for (int j = 0; j < 10; j++) part[j] = 0.f;
    for (int k = threadIdx.x; k < 3675; k += blockDim.x){
        float fv = f[k];
        #pragma unroll
        for (int j = 0; j < 10; j++) part[j] += fv * fcw[(size_t)j*3675 + k];
    }
    __shared__ float sh[10][8];
    int lane = threadIdx.x & 31, wid = threadIdx.x >> 5;
    #pragma unroll
    for (int j = 0; j < 10; j++){
        float v = part[j];
        #pragma unroll
        for (int off = 16; off; off >>= 1) v += __shfl_down_sync(0xffffffffu, v, off);
        if (lane == 0) sh[j][wid] = v;
    }
    __syncthreads();
    if (threadIdx.x < 10){
        float s = 0.f;
        #pragma unroll
        for (int w = 0; w < 8; w++) s += sh[threadIdx.x][w];
        out[b*10 + threadIdx.x] = s + fcb[threadIdx.x];
    }
}

// ---------------- host launcher ----------------
extern "C" void kernel_launch(void* const* d_in, const int* in_sizes, int n_in,
                              void* d_out, int out_size){
    const float* x   = (const float*)d_in[0];
    const float* w1  = (const float*)d_in[1];
    const float* w2  = (const float*)d_in[2];
    const float* w3  = (const float*)d_in[3];
    const float* w4  = (const float*)d_in[4];
    const float* fcw = (const float*)d_in[5];
    const float* fcb = (const float*)d_in[6];
    const float* cb  = (const float*)d_in[7];
    float* out = (float*)d_out;

    // prototype norms
    wnorm_kernel<<<dim3(O1,3), 128>>>(w1, 1, K1);
    wnorm_kernel<<<dim3(O2,3), 128>>>(w2, 2, K2);
    wnorm_kernel<<<dim3(O3,3), 128>>>(w3, 3, K3);
    wnorm_kernel<<<dim3(O4,3), 128>>>(w4, 4, K4);

    // stage 1
    patch1_kernel<<<dim3(BATCH,3), 256>>>(x);
    dist_kernel<<<dim3(M1/64, (O1+63)/64, 3), 256>>>(1, w1, M1, O1, K1);
    reduce_kernel<<<dim3(16, 36, 3), 256>>>(1, M1, O1, 36, 16);
    std_kernel<<<108, 32>>>(36, 16, 409600.0, 0);
    apply1_kernel<<<dim3(M2,3), 128>>>(cb);

    // stage 2
    dist_kernel<<<dim3(M2/64, (O2+63)/64, 3), 256>>>(2, w2, M2, O2, K2);
    reduce_kernel<<<dim3(288, 1, 3), 256>>>(2, M2, O2, 1, 288);
    std_kernel<<<3, 32>>>(1, 288, 8294400.0, 108);
    apply2_kernel<<<dim3(M3,3), 256>>>(cb);

    // stage 3
    dist_kernel<<<dim3(M3/64, (O3+63)/64, 3), 256>>>(3, w3, M3, O3, K3);
    reduce_kernel<<<dim3(96, 1, 3), 256>>>(3, M3, O3, 1, 96);
    std_kernel<<<3, 32>>>(1, 96, 7680000.0, 111);
    apply3_kernel<<<dim3(BATCH,3), 256>>>(cb);

    // stage 4
    dist_kernel<<<dim3(M4/64, (O4+63)/64, 3), 256>>>(4, w4, M4, O4, K4);
    reduce_kernel<<<dim3(64, 1, 3), 256>>>(4, M4, O4, 1, 64);
    std_kernel<<<3, 32>>>(1, 64, 5017600.0, 114);
    apply4_kernel<<<2048, 256>>>(cb);

    // FC head
    fc_kernel<<<BATCH, 256>>>(fcw, fcb, out);
}

// round 4
// speedup vs baseline: 1.4072x; 1.4072x over previous
#include <cuda_runtime.h>
#include <math.h>

// ---------------- problem constants ----------------
#define BATCH 4096
#define M1 147456   // B*36
#define O1 100
#define K1 25
#define M2 36864    // B*9
#define O2 225
#define K2 100
#define M3 12288    // B*3
#define O3 625
#define K3 225
#define M4 4096     // B
#define O4 1225
#define K4 625
#define EPSF 1e-12f

// padded dims for the GEMM (K padded to mult of 16, O padded to mult of 128)
#define KP1 32
#define KP2 112
#define KP3 240
#define KP4 640
#define OP1 128
#define OP2 256
#define OP3 640
#define OP4 1280

// ---------------- device scratch (static, allocation-free) ----------------
__device__ __align__(16) float g_P1[(size_t)3*M1*KP1];
__device__ __align__(16) float g_P2[(size_t)3*M2*KP2];
__device__ __align__(16) float g_P3[(size_t)3*M3*KP3];
__device__ __align__(16) float g_P4[(size_t)3*M4*KP4];
__device__ __align__(16) float g_W1p[(size_t)3*OP1*KP1];
__device__ __align__(16) float g_W2p[(size_t)3*OP2*KP2];
__device__ __align__(16) float g_W3p[(size_t)3*OP3*KP3];
__device__ __align__(16) float g_W4p[(size_t)3*OP4*KP4];
__device__ float g_D1[(size_t)3*M1*O1];
__device__ float g_D2[(size_t)3*M2*O2];
__device__ float g_D3[(size_t)3*M3*O3];
__device__ float g_D4[(size_t)3*M4*O4];
__device__ float g_pn1[(size_t)3*M1];
__device__ float g_pn2[(size_t)3*M2];
__device__ float g_pn3[(size_t)3*M3];
__device__ float g_pn4[(size_t)3*M4];
__device__ float g_wn1[3*OP1];
__device__ float g_wn2[3*OP2];
__device__ float g_wn3[3*OP3];
__device__ float g_wn4[3*OP4];
__device__ float g_feat[(size_t)BATCH*3675];
__device__ double g_partial[8192];
__device__ float g_istd[128];   // [0..107]=stage1 (c*36+win), 108..110 s2, 111..113 s3, 114..116 s4

// ---------------- packed f32x2 helpers ----------------
__device__ __forceinline__ unsigned long long pk2(float lo, float hi){
    unsigned long long r;
    asm("mov.b64 %0, {%1, %2};" : "=l"(r) : "f"(lo), "f"(hi));
    return r;
}
__device__ __forceinline__ void fma2(unsigned long long &acc, unsigned long long a, unsigned long long b){
    asm("fma.rn.f32x2 %0, %1, %2, %0;" : "+l"(acc) : "l"(a), "l"(b));
}
__device__ __forceinline__ float2 upk2(unsigned long long v){
    float2 r;
    asm("mov.b64 {%0, %1}, %2;" : "=f"(r.x), "=f"(r.y) : "l"(v));
    return r;
}

// deterministic block reduce (sum), valid result in thread 0
__device__ __forceinline__ float blockReduceSum(float v){
    __shared__ float sh[32];
    int lane = threadIdx.x & 31;
    int wid  = threadIdx.x >> 5;
    #pragma unroll
    for (int off = 16; off; off >>= 1) v += __shfl_down_sync(0xffffffffu, v, off);
    if (lane == 0) sh[wid] = v;
    __syncthreads();
    float r = 0.f;
    if (wid == 0){
        int nw = (blockDim.x + 31) >> 5;
        r = (lane < nw) ? sh[lane] : 0.f;
        #pragma unroll
        for (int off = 16; off; off >>= 1) r += __shfl_down_sync(0xffffffffu, r, off);
    }
    __syncthreads();
    return r;
}

// ---------------- kernels ----------------

// pack weights into zero-padded (Opad,Kpad) layout + |w|^2. grid (Opad, 3), block 128.
__global__ void packW_kernel(const float* __restrict__ W, float* __restrict__ Wp,
                             float* __restrict__ wn, int O, int Opad, int K, int Kpad){
    int c = blockIdx.y, o = blockIdx.x;
    const float* src = W + ((size_t)c*O + o)*K;
    float* dst = Wp + ((size_t)c*Opad + o)*Kpad;
    float s = 0.f;
    for (int k = threadIdx.x; k < Kpad; k += blockDim.x){
        float v = (o < O && k < K) ? src[k] : 0.f;
        dst[k] = v;
        s += v*v;
    }
    float t = blockReduceSum(s);
    if (threadIdx.x == 0) wn[c*Opad + o] = t;
}

// stage-1 patch extraction (padded K-stride 32) + per-patch norms. grid (B, 3), block 256.
__global__ void patch1_kernel(const float* __restrict__ x){
    __shared__ float img[784];
    int n = blockIdx.x, c = blockIdx.y;
    const float* src = x + ((size_t)n*3 + c)*784;
    for (int i = threadIdx.x; i < 784; i += blockDim.x) img[i] = src[i];
    __syncthreads();
    for (int idx = threadIdx.x; idx < 36*32; idx += blockDim.x){
        int win = idx >> 5, k = idx & 31;
        float v = 0.f;
        if (k < 25){
            int i = win / 6, j = win % 6, r = k / 5, cc = k % 5;
            v = img[(4*i + r)*28 + 4*j + cc];
        }
        g_P1[((size_t)c*M1 + n*36 + win)*KP1 + k] = v;
    }
    if (threadIdx.x < 36){
        int win = threadIdx.x;
        int i = win / 6, j = win % 6;
        float s = 0.f;
        #pragma unroll
        for (int r = 0; r < 5; r++)
            #pragma unroll
            for (int cc = 0; cc < 5; cc++){
                float v = img[(4*i + r)*28 + 4*j + cc];
                s += v*v;
            }
        g_pn1[(size_t)c*M1 + n*36 + win] = s;
    }
}

// distance GEMM with packed f32x2 FMAs.
// D[m][o] = max(|p_m|^2 + |w_o|^2 - 2 p.w, 0) + eps
// 128x128 tile, BK=16, 256 threads, 8x8 microtile (row-pair f32x2 accumulators).
// grid (M/128, Opad/128, 3). Operands fully padded -> guard-free mainloop.
__global__ void __launch_bounds__(256, 2) dist2_kernel(
    const float* __restrict__ Pbase, const float* __restrict__ Wbase,
    const float* __restrict__ pnb, const float* __restrict__ wnb,
    float* __restrict__ Dbase, int M, int O, int Opad, int Kpad)
{
    __shared__ __align__(16) float As[2][16][128];
    __shared__ __align__(16) float Bs[2][16][128];

    const int c = blockIdx.z;
    const float* __restrict__ Pc  = Pbase + (size_t)c*M*Kpad;
    const float* __restrict__ Wc  = Wbase + (size_t)c*Opad*Kpad;
    const float* __restrict__ pnc = pnb + (size_t)c*M;
    const float* __restrict__ wnc = wnb + (size_t)c*Opad;
    float* __restrict__ Dc = Dbase + (size_t)c*M*O;

    const int m0 = blockIdx.x * 128;
    const int o0 = blockIdx.y * 128;
    const int tid = threadIdx.x;
    const int tx = tid & 15, ty = tid >> 4;
    const int r0 = tid >> 2, q = tid & 3;

    unsigned long long acc[4][8];
    #pragma unroll
    for (int i = 0; i < 4; i++)
        #pragma unroll
        for (int j = 0; j < 8; j++) acc[i][j] = 0ULL;

    const int nk = Kpad >> 4;
    const float* pA = Pc + (size_t)(m0 + r0)*Kpad + q*4;
    const float* pB = Wc + (size_t)(o0 + r0)*Kpad + q*4;
    const size_t strideA = (size_t)64*Kpad;

    float4 sa0, sa1, sb0, sb1;

    // prologue: tile 0 -> buf 0
    sa0 = *reinterpret_cast<const float4*>(pA);
    sa1 = *reinterpret_cast<const float4*>(pA + strideA);
    sb0 = *reinterpret_cast<const float4*>(pB);
    sb1 = *reinterpret_cast<const float4*>(pB + strideA);
    {
        int kq = q*4;
        As[0][kq+0][r0] = sa0.x; As[0][kq+1][r0] = sa0.y; As[0][kq+2][r0] = sa0.z; As[0][kq+3][r0] = sa0.w;
        As[0][kq+0][r0+64] = sa1.x; As[0][kq+1][r0+64] = sa1.y; As[0][kq+2][r0+64] = sa1.z; As[0][kq+3][r0+64] = sa1.w;
        Bs[0][kq+0][r0] = sb0.x; Bs[0][kq+1][r0] = sb0.y; Bs[0][kq+2][r0] = sb0.z; Bs[0][kq+3][r0] = sb0.w;
        Bs[0][kq+0][r0+64] = sb1.x; Bs[0][kq+1][r0+64] = sb1.y; Bs[0][kq+2][r0+64] = sb1.z; Bs[0][kq+3][r0+64] = sb1.w;
    }
    __syncthreads();

    int buf = 0;
    for (int kt = 0; kt < nk; kt++){
        if (kt + 1 < nk){
            const float* a = pA + (size_t)(kt+1)*16;
            const float* b = pB + (size_t)(kt+1)*16;
            sa0 = *reinterpret_cast<const float4*>(a);
            sa1 = *reinterpret_cast<const float4*>(a + strideA);
            sb0 = *reinterpret_cast<const float4*>(b);
            sb1 = *reinterpret_cast<const float4*>(b + strideA);
        }
        #pragma unroll
        for (int kk = 0; kk < 16; kk++){
            float4 a0 = *reinterpret_cast<const float4*>(&As[buf][kk][ty*8]);
            float4 a1 = *reinterpret_cast<const float4*>(&As[buf][kk][ty*8+4]);
            float4 b0 = *reinterpret_cast<const float4*>(&Bs[buf][kk][tx*8]);
            float4 b1 = *reinterpret_cast<const float4*>(&Bs[buf][kk][tx*8+4]);
            unsigned long long ap0 = pk2(a0.x, a0.y);
            unsigned long long ap1 = pk2(a0.z, a0.w);
            unsigned long long ap2 = pk2(a1.x, a1.y);
            unsigned long long ap3 = pk2(a1.z, a1.w);
            float bv[8] = {b0.x, b0.y, b0.z, b0.w, b1.x, b1.y, b1.z, b1.w};
            #pragma unroll
            for (int j = 0; j < 8; j++){
                unsigned long long bd = pk2(bv[j], bv[j]);
                fma2(acc[0][j], ap0, bd);
                fma2(acc[1][j], ap1, bd);
                fma2(acc[2][j], ap2, bd);
                fma2(acc[3][j], ap3, bd);
            }
        }
        if (kt + 1 < nk){
            int nb = buf ^ 1;
            int kq = q*4;
            As[nb][kq+0][r0] = sa0.x; As[nb][kq+1][r0] = sa0.y; As[nb][kq+2][r0] = sa0.z; As[nb][kq+3][r0] = sa0.w;
            As[nb][kq+0][r0+64] = sa1.x; As[nb][kq+1][r0+64] = sa1.y; As[nb][kq+2][r0+64] = sa1.z; As[nb][kq+3][r0+64] = sa1.w;
            Bs[nb][kq+0][r0] = sb0.x; Bs[nb][kq+1][r0] = sb0.y; Bs[nb][kq+2][r0] = sb0.z; Bs[nb][kq+3][r0] = sb0.w;
            Bs[nb][kq+0][r0+64] = sb1.x; Bs[nb][kq+1][r0+64] = sb1.y; Bs[nb][kq+2][r0+64] = sb1.z; Bs[nb][kq+3][r0+64] = sb1.w;
        }
        __syncthreads();
        buf ^= 1;
    }

    // epilogue
    float pnr[8], wnr[8];
    #pragma unroll
    for (int i = 0; i < 8; i++) pnr[i] = pnc[m0 + ty*8 + i];
    #pragma unroll
    for (int j = 0; j < 8; j++) wnr[j] = wnc[o0 + tx*8 + j];

    #pragma unroll
    for (int rp = 0; rp < 4; rp++){
        int mA = m0 + ty*8 + rp*2;
        #pragma unroll
        for (int j = 0; j < 8; j++){
            int oo = o0 + tx*8 + j;
            if (oo < O){
                float2 v = upk2(acc[rp][j]);
                float d2a = pnr[rp*2]   + wnr[j] - 2.f*v.x;
                float d2b = pnr[rp*2+1] + wnr[j] - 2.f*v.y;
                Dc[(size_t)mA*O + oo]     = fmaxf(d2a, 0.f) + EPSF;
                Dc[(size_t)(mA+1)*O + oo] = fmaxf(d2b, 0.f) + EPSF;
            }
        }
    }
}

// deterministic partial sums of (sum dist, sum dist^2) per group.
// grid (chunks, G, 3), block 256. rows of group g are m = r*G + g.
__global__ void reduce_kernel(const float* __restrict__ Dbase, int M, int O, int G, int chunks){
    int c = blockIdx.z, g = blockIdx.y, chunk = blockIdx.x;
    const float* Dc = Dbase + (size_t)c*M*O;
    int rpg = M / G;
    int rpc = (rpg + chunks - 1) / chunks;
    int r0 = chunk * rpc;
    int r1 = min(r0 + rpc, rpg);
    float s1 = 0.f, s2 = 0.f;
    for (int r = r0; r < r1; r++){
        const float* row = Dc + ((size_t)(r*G + g))*O;
        for (int o = threadIdx.x; o < O; o += blockDim.x){
            float d2 = row[o];          // = dist^2 exactly
            s2 += d2;
            s1 += sqrtf(d2);
        }
    }
    __shared__ double sh1[256], sh2[256];
    sh1[threadIdx.x] = (double)s1;
    sh2[threadIdx.x] = (double)s2;
    __syncthreads();
    for (int st = 128; st; st >>= 1){
        if (threadIdx.x < st){
            sh1[threadIdx.x] += sh1[threadIdx.x + st];
            sh2[threadIdx.x] += sh2[threadIdx.x + st];
        }
        __syncthreads();
    }
    if (threadIdx.x == 0){
        int slot = (c*G + g)*chunks + chunk;
        g_partial[2*slot]     = sh1[0];
        g_partial[2*slot + 1] = sh2[0];
    }
}

// finalize: istd = 0.5 / var (unbiased). grid 3*G blocks.
__global__ void std_kernel(int G, int chunks, double Mcnt, int base){
    if (threadIdx.x != 0) return;
    int idx = blockIdx.x;   // c*G + g
    double S1 = 0.0, S2 = 0.0;
    for (int i = 0; i < chunks; i++){
        S1 += g_partial[2*(idx*chunks + i)];
        S2 += g_partial[2*(idx*chunks + i) + 1];
    }
    double var = (S2 - S1*S1/Mcnt) / (Mcnt - 1.0);
    g_istd[base + idx] = (float)(0.5 / var);
}

// stage1 epilogue: exp + crelu(0.4) + 2x2 alpha pooling -> P2 rows (padded 112) + norms.
// grid (M2, 3), block 128. n2 = n*9 + h*3 + w.
__global__ void apply1_kernel(const float* __restrict__ cb){
    int c = blockIdx.y, n2 = blockIdx.x;
    int n = n2 / 9, hw = n2 % 9, h = hw / 3, w = hw % 3;
    const float* D1c = g_D1 + (size_t)c*M1*O1;
    const float* is  = g_istd + c*36;
    float bias = cb[0];
    const float A00 = 0.729f, A01 = 0.81f, A10 = 0.9f, A11 = 1.0f;
    int o = threadIdx.x;
    float pooled = 0.f;
    if (o < O1){
        float s = 0.f;
        #pragma unroll
        for (int a = 0; a < 2; a++){
            #pragma unroll
            for (int b = 0; b < 2; b++){
                int win = (2*h + a)*6 + (2*w + b);
                float d2 = D1c[((size_t)(n*36 + win))*O1 + o];
                float y = expf(-d2 * is[win]);
                y = (y >= bias) ? y : 0.f;
                float al = (a == 0) ? ((b == 0) ? A00 : A01) : ((b == 0) ? A10 : A11);
                s += al * y;
            }
        }
        pooled = 0.25f * s;
    }
    if (o < KP2) g_P2[((size_t)c*M2 + n2)*KP2 + o] = pooled;
    float t = blockReduceSum(pooled*pooled);
    if (threadIdx.x == 0) g_pn2[(size_t)c*M2 + n2] = t;
}

// stage2 epilogue: exp + crelu(0.1) + pool over w with alpha [0.81,0.9,1.0]/3. padded K 240.
// grid (M3, 3), block 256. n3 = b*3 + h, src rows n2 = b*9 + h*3 + w.
__global__ void apply2_kernel(const float* __restrict__ cb){
    int c = blockIdx.y, n3 = blockIdx.x;
    int b = n3 / 3, h = n3 % 3;
    const float* D2c = g_D2 + (size_t)c*M2*O2;
    float is = g_istd[108 + c];
    float bias = cb[1];
    const float AW[3] = {0.81f, 0.9f, 1.0f};
    int k = threadIdx.x;
    float v = 0.f;
    if (k < O2){
        float s = 0.f;
        #pragma unroll
        for (int w = 0; w < 3; w++){
            int n2 = b*9 + h*3 + w;
            float d2 = D2c[(size_t)n2*O2 + k];
            float y = expf(-d2 * is);
            y = (y >= bias) ? y : 0.f;
            s += AW[w] * y;
        }
        v = s * (1.f/3.f);
    }
    if (k < KP3) g_P3[((size_t)c*M3 + n3)*KP3 + k] = v;
    float t = blockReduceSum(v*v);
    if (threadIdx.x == 0) g_pn3[(size_t)c*M3 + n3] = t;
}

// stage3 epilogue: exp + crelu(0.01) + pool over h with alpha [0.81,0.9,1.0]/3. padded K 640.
// grid (B, 3), block 256. src rows n3 = b*3 + h.
__global__ void apply3_kernel(const float* __restrict__ cb){
    int c = blockIdx.y, b = blockIdx.x;
    const float* D3c = g_D3 + (size_t)c*M3*O3;
    float is = g_istd[111 + c];
    float bias = cb[2];
    const float AH[3] = {0.81f, 0.9f, 1.0f};
    float sq = 0.f;
    for (int k = threadIdx.x; k < KP4; k += blockDim.x){
        float v = 0.f;
        if (k < O3){
            float s = 0.f;
            #pragma unroll
            for (int h = 0; h < 3; h++){
                float d2 = D3c[((size_t)(b*3 + h))*O3 + k];
                float y = expf(-d2 * is);
                y = (y >= bias) ? y : 0.f;
                s += AH[h] * y;
            }
            v = s * (1.f/3.f);
        }
        g_P4[((size_t)c*M4 + b)*KP4 + k] = v;
        sq += v*v;
    }
    float t = blockReduceSum(sq);
    if (threadIdx.x == 0) g_pn4[(size_t)c*M4 + b] = t;
}

// stage4 epilogue: exp + crelu(0.01) -> feat[b][c*1225+o]. grid-stride.
__global__ void apply4_kernel(const float* __restrict__ cb){
    float bias = cb[3];
    const size_t total = (size_t)3*M4*O4;
    for (size_t idx = (size_t)blockIdx.x*blockDim.x + threadIdx.x; idx < total;
         idx += (size_t)gridDim.x*blockDim.x){
        int c = (int)(idx / ((size_t)M4*O4));
        int r = (int)(idx % ((size_t)M4*O4));
        int b = r / O4, o = r % O4;
        float d2 = g_D4[idx];
        float y = expf(-d2 * g_istd[114 + c]);
        y = (y >= bias) ? y : 0.f;
        g_feat[(size_t)b*3675 + c*1225 + o] = y;
    }
}

// FC: out[b][j] = feat[b] . fcw[j] + fcb[j]. grid B, block 256.
__global__ void fc_kernel(const float* __restrict__ fcw, const float* __restrict__ fcb,
                          float* __restrict__ out){
    int b = blockIdx.x;
    const float* f = g_feat + (size_t)b*3675;
    float part[10];
    #pragma unroll
    for (int j = 0; j < 10; j++) part[j] = 0.f;
    for (int k = threadIdx.x; k < 3675; k += blockDim.x){
        float fv = f[k];
        #pragma unroll
        for (int j = 0; j < 10; j++) part[j] += fv * fcw[(size_t)j*3675 + k];
    }
    __shared__ float sh[10][8];
    int lane = threadIdx.x & 31, wid = threadIdx.x >> 5;
    #pragma unroll
    for (int j = 0; j < 10; j++){
        float v = part[j];
        #pragma unroll
        for (int off = 16; off; off >>= 1) v += __shfl_down_sync(0xffffffffu, v, off);
        if (lane == 0) sh[j][wid] = v;
    }
    __syncthreads();
    if (threadIdx.x < 10){
        float s = 0.f;
        #pragma unroll
        for (int w = 0; w < 8; w++) s += sh[threadIdx.x][w];
        out[b*10 + threadIdx.x] = s + fcb[threadIdx.x];
    }
}

// ---------------- host launcher ----------------
extern "C" void kernel_launch(void* const* d_in, const int* in_sizes, int n_in,
                              void* d_out, int out_size){
    const float* x   = (const float*)d_in[0];
    const float* w1  = (const float*)d_in[1];
    const float* w2  = (const float*)d_in[2];
    const float* w3  = (const float*)d_in[3];
    const float* w4  = (const float*)d_in[4];
    const float* fcw = (const float*)d_in[5];
    const float* fcb = (const float*)d_in[6];
    const float* cb  = (const float*)d_in[7];
    float* out = (float*)d_out;

    float *P1, *P2, *P3, *P4, *W1p, *W2p, *W3p, *W4p;
    float *D1, *D2, *D3, *D4, *pn1, *pn2, *pn3, *pn4, *wn1, *wn2, *wn3, *wn4;
    cudaGetSymbolAddress((void**)&P1, g_P1);   cudaGetSymbolAddress((void**)&P2, g_P2);
    cudaGetSymbolAddress((void**)&P3, g_P3);   cudaGetSymbolAddress((void**)&P4, g_P4);
    cudaGetSymbolAddress((void**)&W1p, g_W1p); cudaGetSymbolAddress((void**)&W2p, g_W2p);
    cudaGetSymbolAddress((void**)&W3p, g_W3p); cudaGetSymbolAddress((void**)&W4p, g_W4p);
    cudaGetSymbolAddress((void**)&D1, g_D1);   cudaGetSymbolAddress((void**)&D2, g_D2);
    cudaGetSymbolAddress((void**)&D3, g_D3);   cudaGetSymbolAddress((void**)&D4, g_D4);
    cudaGetSymbolAddress((void**)&pn1, g_pn1); cudaGetSymbolAddress((void**)&pn2, g_pn2);
    cudaGetSymbolAddress((void**)&pn3, g_pn3); cudaGetSymbolAddress((void**)&pn4, g_pn4);
    cudaGetSymbolAddress((void**)&wn1, g_wn1); cudaGetSymbolAddress((void**)&wn2, g_wn2);
    cudaGetSymbolAddress((void**)&wn3, g_wn3); cudaGetSymbolAddress((void**)&wn4, g_wn4);

    // weight packing + norms
    packW_kernel<<<dim3(OP1,3), 128>>>(w1, W1p, wn1, O1, OP1, K1, KP1);
    packW_kernel<<<dim3(OP2,3), 128>>>(w2, W2p, wn2, O2, OP2, K2, KP2);
    packW_kernel<<<dim3(OP3,3), 128>>>(w3, W3p, wn3, O3, OP3, K3, KP3);
    packW_kernel<<<dim3(OP4,3), 128>>>(w4, W4p, wn4, O4, OP4, K4, KP4);

    // stage 1
    patch1_kernel<<<dim3(BATCH,3), 256>>>(x);
    dist2_kernel<<<dim3(M1/128, OP1/128, 3), 256>>>(P1, W1p, pn1, wn1, D1, M1, O1, OP1, KP1);
    reduce_kernel<<<dim3(16, 36, 3), 256>>>(D1, M1, O1, 36, 16);
    std_kernel<<<108, 32>>>(36, 16, 409600.0, 0);
    apply1_kernel<<<dim3(M2,3), 128>>>(cb);

    // stage 2
    dist2_kernel<<<dim3(M2/128, OP2/128, 3), 256>>>(P2, W2p, pn2, wn2, D2, M2, O2, OP2, KP2);
    reduce_kernel<<<dim3(288, 1, 3), 256>>>(D2, M2, O2, 1, 288);
    std_kernel<<<3, 32>>>(1, 288, 8294400.0, 108);
    apply2_kernel<<<dim3(M3,3), 256>>>(cb);

    // stage 3
    dist2_kernel<<<dim3(M3/128, OP3/128, 3), 256>>>(P3, W3p, pn3, wn3, D3, M3, O3, OP3, KP3);
    reduce_kernel<<<dim3(96, 1, 3), 256>>>(D3, M3, O3, 1, 96);
    std_kernel<<<3, 32>>>(1, 96, 7680000.0, 111);
    apply3_kernel<<<dim3(BATCH,3), 256>>>(cb);

    // stage 4
    dist2_kernel<<<dim3(M4/128, OP4/128, 3), 256>>>(P4, W4p, pn4, wn4, D4, M4, O4, OP4, KP4);
    reduce_kernel<<<dim3(64, 1, 3), 256>>>(D4, M4, O4, 1, 64);
    std_kernel<<<3, 32>>>(1, 64, 5017600.0, 114);
    apply4_kernel<<<2048, 256>>>(cb);

    // FC head
    fc_kernel<<<BATCH, 256>>>(fcw, fcb, out);
}

// round 8
// speedup vs baseline: 1.6309x; 1.1590x over previous
#include <cuda_runtime.h>
#include <math.h>

// ---------------- problem constants ----------------
#define BATCH 4096
#define M1 147456   // B*36
#define O1 100
#define K1 25
#define M2 36864    // B*9
#define O2 225
#define K2 100
#define M3 12288    // B*3
#define O3 625
#define K3 225
#define M4 4096     // B
#define O4 1225
#define K4 625
#define EPSF 1e-12f

// padded dims for the GEMM (K padded to mult of 16, O padded to mult of 128)
#define KP1 32
#define KP2 112
#define KP3 240
#define KP4 640
#define OP1 128
#define OP2 256
#define OP3 640
#define OP4 1280

// ---------------- device scratch (static, allocation-free) ----------------
__device__ __align__(16) float g_P1[(size_t)3*M1*KP1];
__device__ __align__(16) float g_P2[(size_t)3*M2*KP2];
__device__ __align__(16) float g_P3[(size_t)3*M3*KP3];
__device__ __align__(16) float g_P4[(size_t)3*M4*KP4];
__device__ __align__(16) float g_W1p[(size_t)3*OP1*KP1];
__device__ __align__(16) float g_W2p[(size_t)3*OP2*KP2];
__device__ __align__(16) float g_W3p[(size_t)3*OP3*KP3];
__device__ __align__(16) float g_W4p[(size_t)3*OP4*KP4];
__device__ float g_D1[(size_t)3*M1*O1];
__device__ float g_D2[(size_t)3*M2*O2];
__device__ float g_D3[(size_t)3*M3*O3];
__device__ float g_D4[(size_t)3*M4*O4];
__device__ float g_pn1[(size_t)3*M1];
__device__ float g_pn2[(size_t)3*M2];
__device__ float g_pn3[(size_t)3*M3];
__device__ float g_pn4[(size_t)3*M4];
__device__ float g_wn1[3*OP1];
__device__ float g_wn2[3*OP2];
__device__ float g_wn3[3*OP3];
__device__ float g_wn4[3*OP4];
__device__ float g_feat[(size_t)BATCH*3675];
__device__ double g_partial[8192];
__device__ float g_istd[128];   // [0..107]=stage1 (c*36+win), 108..110 s2, 111..113 s3, 114..116 s4

// ---------------- packed f32x2 helpers ----------------
__device__ __forceinline__ unsigned long long pk2(float lo, float hi){
    unsigned long long r;
    asm("mov.b64 %0, {%1, %2};" : "=l"(r) : "f"(lo), "f"(hi));
    return r;
}
__device__ __forceinline__ void fma2(unsigned long long &acc, unsigned long long a, unsigned long long b){
    asm("fma.rn.f32x2 %0, %1, %2, %0;" : "+l"(acc) : "l"(a), "l"(b));
}
__device__ __forceinline__ float2 upk2(unsigned long long v){
    float2 r;
    asm("mov.b64 {%0, %1}, %2;" : "=f"(r.x), "=f"(r.y) : "l"(v));
    return r;
}

// deterministic block reduce (sum), valid result in thread 0
__device__ __forceinline__ float blockReduceSum(float v){
    __shared__ float sh[32];
    int lane = threadIdx.x & 31;
    int wid  = threadIdx.x >> 5;
    #pragma unroll
    for (int off = 16; off; off >>= 1) v += __shfl_down_sync(0xffffffffu, v, off);
    if (lane == 0) sh[wid] = v;
    __syncthreads();
    float r = 0.f;
    if (wid == 0){
        int nw = (blockDim.x + 31) >> 5;
        r = (lane < nw) ? sh[lane] : 0.f;
        #pragma unroll
        for (int off = 16; off; off >>= 1) r += __shfl_down_sync(0xffffffffu, r, off);
    }
    __syncthreads();
    return r;
}

// ---------------- kernels ----------------

// pack weights into zero-padded (Opad,Kpad) layout + |w|^2. grid (Opad, 3), block 128.
__global__ void packW_kernel(const float* __restrict__ W, float* __restrict__ Wp,
                             float* __restrict__ wn, int O, int Opad, int K, int Kpad){
    int c = blockIdx.y, o = blockIdx.x;
    const float* src = W + ((size_t)c*O + o)*K;
    float* dst = Wp + ((size_t)c*Opad + o)*Kpad;
    float s = 0.f;
    for (int k = threadIdx.x; k < Kpad; k += blockDim.x){
        float v = (o < O && k < K) ? src[k] : 0.f;
        dst[k] = v;
        s += v*v;
    }
    float t = blockReduceSum(s);
    if (threadIdx.x == 0) wn[c*Opad + o] = t;
}

// stage-1 patch extraction (padded K-stride 32) + per-patch norms. grid (B, 3), block 256.
__global__ void patch1_kernel(const float* __restrict__ x){
    __shared__ float img[784];
    int n = blockIdx.x, c = blockIdx.y;
    const float* src = x + ((size_t)n*3 + c)*784;
    for (int i = threadIdx.x; i < 784; i += blockDim.x) img[i] = src[i];
    __syncthreads();
    for (int idx = threadIdx.x; idx < 36*32; idx += blockDim.x){
        int win = idx >> 5, k = idx & 31;
        float v = 0.f;
        if (k < 25){
            int i = win / 6, j = win % 6, r = k / 5, cc = k % 5;
            v = img[(4*i + r)*28 + 4*j + cc];
        }
        g_P1[((size_t)c*M1 + n*36 + win)*KP1 + k] = v;
    }
    if (threadIdx.x < 36){
        int win = threadIdx.x;
        int i = win / 6, j = win % 6;
        float s = 0.f;
        #pragma unroll
        for (int r = 0; r < 5; r++)
            #pragma unroll
            for (int cc = 0; cc < 5; cc++){
                float v = img[(4*i + r)*28 + 4*j + cc];
                s += v*v;
            }
        g_pn1[(size_t)c*M1 + n*36 + win] = s;
    }
}

// distance GEMM with packed f32x2 FMAs.
// D[m][o] = max(|p_m|^2 + |w_o|^2 - 2 p.w, 0) + eps
// 128x128 tile, BK=16, 256 threads, 8x8 microtile in split-4+4 (conflict-free)
// fragment mapping: rows {ty*4+i, 64+ty*4+i}, cols {tx*4+j, 64+tx*4+j}.
// grid (M/128, Opad/128, 3). Operands fully padded -> guard-free mainloop.
__global__ void __launch_bounds__(256, 2) dist2_kernel(
    const float* __restrict__ Pbase, const float* __restrict__ Wbase,
    const float* __restrict__ pnb, const float* __restrict__ wnb,
    float* __restrict__ Dbase, int M, int O, int Opad, int Kpad)
{
    __shared__ __align__(16) float As[2][16][128];
    __shared__ __align__(16) float Bs[2][16][128];

    const int c = blockIdx.z;
    const float* __restrict__ Pc  = Pbase + (size_t)c*M*Kpad;
    const float* __restrict__ Wc  = Wbase + (size_t)c*Opad*Kpad;
    const float* __restrict__ pnc = pnb + (size_t)c*M;
    const float* __restrict__ wnc = wnb + (size_t)c*Opad;
    float* __restrict__ Dc = Dbase + (size_t)c*M*O;

    const int m0 = blockIdx.x * 128;
    const int o0 = blockIdx.y * 128;
    const int tid = threadIdx.x;
    const int tx = tid & 15, ty = tid >> 4;
    const int r0 = tid >> 2, q = tid & 3;

    unsigned long long acc[4][8];
    #pragma unroll
    for (int i = 0; i < 4; i++)
        #pragma unroll
        for (int j = 0; j < 8; j++) acc[i][j] = 0ULL;

    const int nk = Kpad >> 4;
    const float* pA = Pc + (size_t)(m0 + r0)*Kpad + q*4;
    const float* pB = Wc + (size_t)(o0 + r0)*Kpad + q*4;
    const size_t strideA = (size_t)64*Kpad;

    float4 sa0, sa1, sb0, sb1;

    // prologue: tile 0 -> buf 0
    sa0 = *reinterpret_cast<const float4*>(pA);
    sa1 = *reinterpret_cast<const float4*>(pA + strideA);
    sb0 = *reinterpret_cast<const float4*>(pB);
    sb1 = *reinterpret_cast<const float4*>(pB + strideA);
    {
        int kq = q*4;
        As[0][kq+0][r0] = sa0.x; As[0][kq+1][r0] = sa0.y; As[0][kq+2][r0] = sa0.z; As[0][kq+3][r0] = sa0.w;
        As[0][kq+0][r0+64] = sa1.x; As[0][kq+1][r0+64] = sa1.y; As[0][kq+2][r0+64] = sa1.z; As[0][kq+3][r0+64] = sa1.w;
        Bs[0][kq+0][r0] = sb0.x; Bs[0][kq+1][r0] = sb0.y; Bs[0][kq+2][r0] = sb0.z; Bs[0][kq+3][r0] = sb0.w;
        Bs[0][kq+0][r0+64] = sb1.x; Bs[0][kq+1][r0+64] = sb1.y; Bs[0][kq+2][r0+64] = sb1.z; Bs[0][kq+3][r0+64] = sb1.w;
    }
    __syncthreads();

    int buf = 0;
    for (int kt = 0; kt < nk; kt++){
        if (kt + 1 < nk){
            const float* a = pA + (size_t)(kt+1)*16;
            const float* b = pB + (size_t)(kt+1)*16;
            sa0 = *reinterpret_cast<const float4*>(a);
            sa1 = *reinterpret_cast<const float4*>(a + strideA);
            sb0 = *reinterpret_cast<const float4*>(b);
            sb1 = *reinterpret_cast<const float4*>(b + strideA);
        }
        #pragma unroll
        for (int kk = 0; kk < 16; kk++){
            // split 4+4 fragments: conflict-free B (16B lane stride), broadcast A
            float4 a0 = *reinterpret_cast<const float4*>(&As[buf][kk][ty*4]);
            float4 a1 = *reinterpret_cast<const float4*>(&As[buf][kk][64 + ty*4]);
            float4 b0 = *reinterpret_cast<const float4*>(&Bs[buf][kk][tx*4]);
            float4 b1 = *reinterpret_cast<const float4*>(&Bs[buf][kk][64 + tx*4]);
            unsigned long long ap0 = pk2(a0.x, a0.y);
            unsigned long long ap1 = pk2(a0.z, a0.w);
            unsigned long long ap2 = pk2(a1.x, a1.y);
            unsigned long long ap3 = pk2(a1.z, a1.w);
            float bv[8] = {b0.x, b0.y, b0.z, b0.w, b1.x, b1.y, b1.z, b1.w};
            #pragma unroll
            for (int j = 0; j < 8; j++){
                unsigned long long bd = pk2(bv[j], bv[j]);
                fma2(acc[0][j], ap0, bd);
                fma2(acc[1][j], ap1, bd);
                fma2(acc[2][j], ap2, bd);
                fma2(acc[3][j], ap3, bd);
            }
        }
        if (kt + 1 < nk){
            int nb = buf ^ 1;
            int kq = q*4;
            As[nb][kq+0][r0] = sa0.x; As[nb][kq+1][r0] = sa0.y; As[nb][kq+2][r0] = sa0.z; As[nb][kq+3][r0] = sa0.w;
            As[nb][kq+0][r0+64] = sa1.x; As[nb][kq+1][r0+64] = sa1.y; As[nb][kq+2][r0+64] = sa1.z; As[nb][kq+3][r0+64] = sa1.w;
            Bs[nb][kq+0][r0] = sb0.x; Bs[nb][kq+1][r0] = sb0.y; Bs[nb][kq+2][r0] = sb0.z; Bs[nb][kq+3][r0] = sb0.w;
            Bs[nb][kq+0][r0+64] = sb1.x; Bs[nb][kq+1][r0+64] = sb1.y; Bs[nb][kq+2][r0+64] = sb1.z; Bs[nb][kq+3][r0+64] = sb1.w;
        }
        __syncthreads();
        buf ^= 1;
    }

    // epilogue: rows {ty*4+i, 64+ty*4+i}, cols {tx*4+j, 64+tx*4+j}
    float pnr[8], wnr[8];
    #pragma unroll
    for (int i = 0; i < 4; i++){
        pnr[i]     = pnc[m0 + ty*4 + i];
        pnr[4 + i] = pnc[m0 + 64 + ty*4 + i];
    }
    #pragma unroll
    for (int j = 0; j < 4; j++){
        wnr[j]     = wnc[o0 + tx*4 + j];
        wnr[4 + j] = wnc[o0 + 64 + tx*4 + j];
    }

    #pragma unroll
    for (int rp = 0; rp < 4; rp++){
        int rbase = (rp < 2) ? (ty*4 + rp*2) : (64 + ty*4 + (rp - 2)*2);
        int mA = m0 + rbase;
        #pragma unroll
        for (int j = 0; j < 8; j++){
            int oo = o0 + ((j < 4) ? (tx*4 + j) : (64 + tx*4 + (j - 4)));
            if (oo < O){
                float2 v = upk2(acc[rp][j]);
                float d2a = pnr[rp*2]   + wnr[j] - 2.f*v.x;
                float d2b = pnr[rp*2+1] + wnr[j] - 2.f*v.y;
                Dc[(size_t)mA*O + oo]     = fmaxf(d2a, 0.f) + EPSF;
                Dc[(size_t)(mA+1)*O + oo] = fmaxf(d2b, 0.f) + EPSF;
            }
        }
    }
}

// deterministic partial sums of (sum dist, sum dist^2) per group.
// grid (chunks, G, 3), block 256. rows of group g are m = r*G + g.
__global__ void reduce_kernel(const float* __restrict__ Dbase, int M, int O, int G, int chunks){
    int c = blockIdx.z, g = blockIdx.y, chunk = blockIdx.x;
    const float* Dc = Dbase + (size_t)c*M*O;
    int rpg = M / G;
    int rpc = (rpg + chunks - 1) / chunks;
    int r0 = chunk * rpc;
    int r1 = min(r0 + rpc, rpg);
    float s1 = 0.f, s2 = 0.f;
    for (int r = r0; r < r1; r++){
        const float* row = Dc + ((size_t)(r*G + g))*O;
        for (int o = threadIdx.x; o < O; o += blockDim.x){
            float d2 = row[o];          // = dist^2 exactly
            s2 += d2;
            s1 += sqrtf(d2);
        }
    }
    __shared__ double sh1[256], sh2[256];
    sh1[threadIdx.x] = (double)s1;
    sh2[threadIdx.x] = (double)s2;
    __syncthreads();
    for (int st = 128; st; st >>= 1){
        if (threadIdx.x < st){
            sh1[threadIdx.x] += sh1[threadIdx.x + st];
            sh2[threadIdx.x] += sh2[threadIdx.x + st];
        }
        __syncthreads();
    }
    if (threadIdx.x == 0){
        int slot = (c*G + g)*chunks + chunk;
        g_partial[2*slot]     = sh1[0];
        g_partial[2*slot + 1] = sh2[0];
    }
}

// finalize: istd = 0.5 / var (unbiased). grid 3*G blocks.
__global__ void std_kernel(int G, int chunks, double Mcnt, int base){
    if (threadIdx.x != 0) return;
    int idx = blockIdx.x;   // c*G + g
    double S1 = 0.0, S2 = 0.0;
    for (int i = 0; i < chunks; i++){
        S1 += g_partial[2*(idx*chunks + i)];
        S2 += g_partial[2*(idx*chunks + i) + 1];
    }
    double var = (S2 - S1*S1/Mcnt) / (Mcnt - 1.0);
    g_istd[base + idx] = (float)(0.5 / var);
}

// stage1 epilogue: exp + crelu(0.4) + 2x2 alpha pooling -> P2 rows (padded 112) + norms.
// grid (M2, 3), block 128. n2 = n*9 + h*3 + w.
__global__ void apply1_kernel(const float* __restrict__ cb){
    int c = blockIdx.y, n2 = blockIdx.x;
    int n = n2 / 9, hw = n2 % 9, h = hw / 3, w = hw % 3;
    const float* D1c = g_D1 + (size_t)c*M1*O1;
    const float* is  = g_istd + c*36;
    float bias = cb[0];
    const float A00 = 0.729f, A01 = 0.81f, A10 = 0.9f, A11 = 1.0f;
    int o = threadIdx.x;
    float pooled = 0.f;
    if (o < O1){
        float s = 0.f;
        #pragma unroll
        for (int a = 0; a < 2; a++){
            #pragma unroll
            for (int b = 0; b < 2; b++){
                int win = (2*h + a)*6 + (2*w + b);
                float d2 = D1c[((size_t)(n*36 + win))*O1 + o];
                float y = expf(-d2 * is[win]);
                y = (y >= bias) ? y : 0.f;
                float al = (a == 0) ? ((b == 0) ? A00 : A01) : ((b == 0) ? A10 : A11);
                s += al * y;
            }
        }
        pooled = 0.25f * s;
    }
    if (o < KP2) g_P2[((size_t)c*M2 + n2)*KP2 + o] = pooled;
    float t = blockReduceSum(pooled*pooled);
    if (threadIdx.x == 0) g_pn2[(size_t)c*M2 + n2] = t;
}

// stage2 epilogue: exp + crelu(0.1) + pool over w with alpha [0.81,0.9,1.0]/3. padded K 240.
// grid (M3, 3), block 256. n3 = b*3 + h, src rows n2 = b*9 + h*3 + w.
__global__ void apply2_kernel(const float* __restrict__ cb){
    int c = blockIdx.y, n3 = blockIdx.x;
    int b = n3 / 3, h = n3 % 3;
    const float* D2c = g_D2 + (size_t)c*M2*O2;
    float is = g_istd[108 + c];
    float bias = cb[1];
    const float AW[3] = {0.81f, 0.9f, 1.0f};
    int k = threadIdx.x;
    float v = 0.f;
    if (k < O2){
        float s = 0.f;
        #pragma unroll
        for (int w = 0; w < 3; w++){
            int n2 = b*9 + h*3 + w;
            float d2 = D2c[(size_t)n2*O2 + k];
            float y = expf(-d2 * is);
            y = (y >= bias) ? y : 0.f;
            s += AW[w] * y;
        }
        v = s * (1.f/3.f);
    }
    if (k < KP3) g_P3[((size_t)c*M3 + n3)*KP3 + k] = v;
    float t = blockReduceSum(v*v);
    if (threadIdx.x == 0) g_pn3[(size_t)c*M3 + n3] = t;
}

// stage3 epilogue: exp + crelu(0.01) + pool over h with alpha [0.81,0.9,1.0]/3. padded K 640.
// grid (B, 3), block 256. src rows n3 = b*3 + h.
__global__ void apply3_kernel(const float* __restrict__ cb){
    int c = blockIdx.y, b = blockIdx.x;
    const float* D3c = g_D3 + (size_t)c*M3*O3;
    float is = g_istd[111 + c];
    float bias = cb[2];
    const float AH[3] = {0.81f, 0.9f, 1.0f};
    float sq = 0.f;
    for (int k = threadIdx.x; k < KP4; k += blockDim.x){
        float v = 0.f;
        if (k < O3){
            float s = 0.f;
            #pragma unroll
            for (int h = 0; h < 3; h++){
                float d2 = D3c[((size_t)(b*3 + h))*O3 + k];
                float y = expf(-d2 * is);
                y = (y >= bias) ? y : 0.f;
                s += AH[h] * y;
            }
            v = s * (1.f/3.f);
        }
        g_P4[((size_t)c*M4 + b)*KP4 + k] = v;
        sq += v*v;
    }
    float t = blockReduceSum(sq);
    if (threadIdx.x == 0) g_pn4[(size_t)c*M4 + b] = t;
}

// stage4 epilogue: exp + crelu(0.01) -> feat[b][c*1225+o]. grid-stride.
__global__ void apply4_kernel(const float* __restrict__ cb){
    float bias = cb[3];
    const size_t total = (size_t)3*M4*O4;
    for (size_t idx = (size_t)blockIdx.x*blockDim.x + threadIdx.x; idx < total;
         idx += (size_t)gridDim.x*blockDim.x){
        int c = (int)(idx / ((size_t)M4*O4));
        int r = (int)(idx % ((size_t)M4*O4));
        int b = r / O4, o = r % O4;
        float d2 = g_D4[idx];
        float y = expf(-d2 * g_istd[114 + c]);
        y = (y >= bias) ? y : 0.f;
        g_feat[(size_t)b*3675 + c*1225 + o] = y;
    }
}

// FC: out[b][j] = feat[b] . fcw[j] + fcb[j]. grid B, block 256.
__global__ void fc_kernel(const float* __restrict__ fcw, const float* __restrict__ fcb,
                          float* __restrict__ out){
    int b = blockIdx.x;
    const float* f = g_feat + (size_t)b*3675;
    float part[10];
    #pragma unroll
    for (int j = 0; j < 10; j++) part[j] = 0.f;
    for (int k = threadIdx.x; k < 3675; k += blockDim.x){
        float fv = f[k];
        #pragma unroll
        for (int j = 0; j < 10; j++) part[j] += fv * fcw[(size_t)j*3675 + k];
    }
    __shared__ float sh[10][8];
    int lane = threadIdx.x & 31, wid = threadIdx.x >> 5;
    #pragma unroll
    for (int j = 0; j < 10; j++){
        float v = part[j];
        #pragma unroll
        for (int off = 16; off; off >>= 1) v += __shfl_down_sync(0xffffffffu, v, off);
        if (lane == 0) sh[j][wid] = v;
    }
    __syncthreads();
    if (threadIdx.x < 10){
        float s = 0.f;
        #pragma unroll
        for (int w = 0; w < 8; w++) s += sh[threadIdx.x][w];
        out[b*10 + threadIdx.x] = s + fcb[threadIdx.x];
    }
}

// ---------------- host launcher ----------------
extern "C" void kernel_launch(void* const* d_in, const int* in_sizes, int n_in,
                              void* d_out, int out_size){
    const float* x   = (const float*)d_in[0];
    const float* w1  = (const float*)d_in[1];
    const float* w2  = (const float*)d_in[2];
    const float* w3  = (const float*)d_in[3];
    const float* w4  = (const float*)d_in[4];
    const float* fcw = (const float*)d_in[5];
    const float* fcb = (const float*)d_in[6];
    const float* cb  = (const float*)d_in[7];
    float* out = (float*)d_out;

    float *P1, *P2, *P3, *P4, *W1p, *W2p, *W3p, *W4p;
    float *D1, *D2, *D3, *D4, *pn1, *pn2, *pn3, *pn4, *wn1, *wn2, *wn3, *wn4;
    cudaGetSymbolAddress((void**)&P1, g_P1);   cudaGetSymbolAddress((void**)&P2, g_P2);
    cudaGetSymbolAddress((void**)&P3, g_P3);   cudaGetSymbolAddress((void**)&P4, g_P4);
    cudaGetSymbolAddress((void**)&W1p, g_W1p); cudaGetSymbolAddress((void**)&W2p, g_W2p);
    cudaGetSymbolAddress((void**)&W3p, g_W3p); cudaGetSymbolAddress((void**)&W4p, g_W4p);
    cudaGetSymbolAddress((void**)&D1, g_D1);   cudaGetSymbolAddress((void**)&D2, g_D2);
    cudaGetSymbolAddress((void**)&D3, g_D3);   cudaGetSymbolAddress((void**)&D4, g_D4);
    cudaGetSymbolAddress((void**)&pn1, g_pn1); cudaGetSymbolAddress((void**)&pn2, g_pn2);
    cudaGetSymbolAddress((void**)&pn3, g_pn3); cudaGetSymbolAddress((void**)&pn4, g_pn4);
    cudaGetSymbolAddress((void**)&wn1, g_wn1); cudaGetSymbolAddress((void**)&wn2, g_wn2);
    cudaGetSymbolAddress((void**)&wn3, g_wn3); cudaGetSymbolAddress((void**)&wn4, g_wn4);

    // weight packing + norms
    packW_kernel<<<dim3(OP1,3), 128>>>(w1, W1p, wn1, O1, OP1, K1, KP1);
    packW_kernel<<<dim3(OP2,3), 128>>>(w2, W2p, wn2, O2, OP2, K2, KP2);
    packW_kernel<<<dim3(OP3,3), 128>>>(w3, W3p, wn3, O3, OP3, K3, KP3);
    packW_kernel<<<dim3(OP4,3), 128>>>(w4, W4p, wn4, O4, OP4, K4, KP4);

    // stage 1
    patch1_kernel<<<dim3(BATCH,3), 256>>>(x);
    dist2_kernel<<<dim3(M1/128, OP1/128, 3), 256>>>(P1, W1p, pn1, wn1, D1, M1, O1, OP1, KP1);
    reduce_kernel<<<dim3(16, 36, 3), 256>>>(D1, M1, O1, 36, 16);
    std_kernel<<<108, 32>>>(36, 16, 409600.0, 0);
    apply1_kernel<<<dim3(M2,3), 128>>>(cb);

    // stage 2
    dist2_kernel<<<dim3(M2/128, OP2/128, 3), 256>>>(P2, W2p, pn2, wn2, D2, M2, O2, OP2, KP2);
    reduce_kernel<<<dim3(288, 1, 3), 256>>>(D2, M2, O2, 1, 288);
    std_kernel<<<3, 32>>>(1, 288, 8294400.0, 108);
    apply2_kernel<<<dim3(M3,3), 256>>>(cb);

    // stage 3
    dist2_kernel<<<dim3(M3/128, OP3/128, 3), 256>>>(P3, W3p, pn3, wn3, D3, M3, O3, OP3, KP3);
    reduce_kernel<<<dim3(96, 1, 3), 256>>>(D3, M3, O3, 1, 96);
    std_kernel<<<3, 32>>>(1, 96, 7680000.0, 111);
    apply3_kernel<<<dim3(BATCH,3), 256>>>(cb);

    // stage 4
    dist2_kernel<<<dim3(M4/128, OP4/128, 3), 256>>>(P4, W4p, pn4, wn4, D4, M4, O4, OP4, KP4);
    reduce_kernel<<<dim3(64, 1, 3), 256>>>(D4, M4, O4, 1, 64);
    std_kernel<<<3, 32>>>(1, 64, 5017600.0, 114);
    apply4_kernel<<<2048, 256>>>(cb);

    // FC head
    fc_kernel<<<BATCH, 256>>>(fcw, fcb, out);
}